// round 14
// baseline (speedup 1.0000x reference)
#include <cuda_runtime.h>
#include <cuda_bf16.h>

#define IMAGE_TOKEN_ID 31999
#define BB 4
#define LL 1024
#define DD 2048
#define NUM_VIS 576
#define NEW_LEN (LL - 1 + NUM_VIS)   // 1599
#define D4 (DD / 4)                  // 512 float4 per row
#define MERGED_ROWS (BB * NEW_LEN)   // 6396
#define MERGED_ELEMS (MERGED_ROWS * DD)
#define ROWS_PER_CTA 12              // 6396 = 533 * 12 exactly
#define ROW_CTAS (MERGED_ROWS / ROWS_PER_CTA)   // 533
#define ITERS 6                      // 12 rows = 6 iterations x 2 rows

// Zero source row for the duplicate-scatter case (static -> zero-initialized).
__device__ float4 g_zero[D4];

// Evict-first store: keep the 52 MB output stream from thrashing L2 read lines.
__device__ __forceinline__ void stg_cs(float4* p, float4 v) {
    asm volatile("st.global.cs.v4.f32 [%0], {%1,%2,%3,%4};"
                 :: "l"(p), "f"(v.x), "f"(v.y), "f"(v.z), "f"(v.w) : "memory");
}

// Scan one batch row's 1024 ids with a single int4 load per thread.
__device__ __forceinline__ void scan_row(const int4* __restrict__ row_ids4,
                                         int t, int* s_slot) {
    int4 w = row_ids4[t];                  // ids[4t .. 4t+3]
    int pos = -1;
    if (w.x == IMAGE_TOKEN_ID) pos = 4 * t;
    if (w.y == IMAGE_TOKEN_ID) pos = 4 * t + 1;
    if (w.z == IMAGE_TOKEN_ID) pos = 4 * t + 2;
    if (w.w == IMAGE_TOKEN_ID) pos = 4 * t + 3;
    if (pos >= 0) atomicMax(s_slot, pos);  // exactly one match per row
}

// Route output row (b, j) with image position p to a source pointer.
__device__ __forceinline__ const float4* route_row(
    int b, int j, int p,
    const int* __restrict__ ids,
    const float4* __restrict__ vis,
    const float4* __restrict__ embed)
{
    if (j >= p && j < p + NUM_VIS) {
        return vis + ((size_t)b * NUM_VIS + (j - p)) * D4;
    }
    if (j == 0 && p != 0) {
        // reference's duplicate-scatter: image row's dummy zero-write to slot 0
        // lands after text position 0's write (XLA in-order scatter).
        return g_zero;
    }
    int i = (j < p) ? j : (j - NUM_VIS + 1);
    return embed + (size_t)ids[b * LL + i] * D4;
}

// Single-wave persistent kernel: 25 tail blocks + 533 payload CTAs = 558
// CTAs, all resident at once (<= 148 SMs x 4 CTAs). Each payload CTA scans
// all 4 batch rows ONCE (one barrier total), then streams 6 sync-free
// iterations of 2 rows (4 LDG.128 + 4 evict-first STG.128 each).
__global__ void __launch_bounds__(256) merge_kernel(
    const int*    __restrict__ ids,    // [B, L]
    const float4* __restrict__ vis,    // [B, NUM_VIS, D/4]
    const float4* __restrict__ embed,  // [32768, D/4]
    float4*       __restrict__ out,    // [B, NEW_LEN, D/4] (+ tail)
    int tail_n, int tail_blocks)
{
    int blk = blockIdx.x;
    int t = threadIdx.x;

    if (blk < tail_blocks) {
        // position_ids tail: broadcast arange(NEW_LEN), as output dtype (fp32)
        int i = blk * 256 + t;
        if (i < tail_n) {
            float* tail = (float*)out + (size_t)MERGED_ELEMS;
            tail[i] = (float)(i % NEW_LEN);
        }
        return;
    }
    blk -= tail_blocks;

    // ---- scan all 4 batch rows once; one barrier for the whole CTA ----
    __shared__ int s_p[BB];
    if (t < BB) s_p[t] = 0;
    __syncthreads();
    #pragma unroll
    for (int bb = 0; bb < BB; bb++) {
        scan_row((const int4*)(ids + bb * LL), t, &s_p[bb]);
    }
    __syncthreads();

    // ---- 6 sync-free iterations of 2 rows ----
    int base = blk * ROWS_PER_CTA;
    #pragma unroll 1
    for (int it = 0; it < ITERS; it++) {
        int row0 = base + it * 2;

        int b0 = row0 / NEW_LEN, j0 = row0 - b0 * NEW_LEN;
        int b1 = (row0 + 1) / NEW_LEN, j1 = (row0 + 1) - b1 * NEW_LEN;

        const float4* s0 = route_row(b0, j0, s_p[b0], ids, vis, embed);
        const float4* s1 = route_row(b1, j1, s_p[b1], ids, vis, embed);

        float4 v00 = s0[t];
        float4 v01 = s0[t + 256];
        float4 v10 = s1[t];
        float4 v11 = s1[t + 256];

        float4* dst = out + (size_t)row0 * D4;
        stg_cs(dst + t,            v00);
        stg_cs(dst + t + 256,      v01);
        stg_cs(dst + D4 + t,       v10);
        stg_cs(dst + D4 + t + 256, v11);
    }
}

extern "C" void kernel_launch(void* const* d_in, const int* in_sizes, int n_in,
                              void* d_out, int out_size) {
    const int*    ids   = (const int*)d_in[0];            // [B, L] int32
    const float4* vis   = (const float4*)d_in[1];         // [B, NUM_VIS, D]
    const float4* embed = (const float4*)d_in[2];         // [32768, D]

    int tail_n = out_size - MERGED_ELEMS;
    if (tail_n < 0) tail_n = 0;
    int tail_blocks = (tail_n + 255) / 256;

    merge_kernel<<<ROW_CTAS + tail_blocks, 256>>>(
        ids, vis, embed, (float4*)d_out, tail_n, tail_blocks);
}